// round 1
// baseline (speedup 1.0000x reference)
#include <cuda_runtime.h>
#include <cstdint>
#include <cstddef>

#define N_ROWS 4096
#define D 512
#define TWO_N 8192
#define T_DROP 409

// Scratch (allocation-free rule: __device__ globals)
__device__ float g_G[(size_t)TWO_N * D];          // 16 MB normalized [h1n; h2n]
__device__ float g_S[(size_t)TWO_N * TWO_N];      // 256 MB Gram matrix
__device__ float g_rowlog[TWO_N];                 // log of per-row middle exp-sum

// ---------------------------------------------------------------------------
// 1) Row L2-normalize h1/h2 into G
// ---------------------------------------------------------------------------
__global__ void normalize_kernel(const float* __restrict__ h1,
                                 const float* __restrict__ h2) {
    int row = blockIdx.x;
    const float* src = (row < N_ROWS) ? (h1 + (size_t)row * D)
                                      : (h2 + (size_t)(row - N_ROWS) * D);
    int tid = threadIdx.x;  // 128 threads, one float4 each (512 floats)
    float4 v = ((const float4*)src)[tid];
    float ss = v.x * v.x + v.y * v.y + v.z * v.z + v.w * v.w;
#pragma unroll
    for (int o = 16; o; o >>= 1) ss += __shfl_xor_sync(0xffffffffu, ss, o);
    __shared__ float wsum[4];
    if ((tid & 31) == 0) wsum[tid >> 5] = ss;
    __syncthreads();
    float tot = wsum[0] + wsum[1] + wsum[2] + wsum[3];
    float inv = 1.0f / fmaxf(sqrtf(tot), 1e-12f);
    v.x *= inv; v.y *= inv; v.z *= inv; v.w *= inv;
    ((float4*)(g_G + (size_t)row * D))[tid] = v;
}

// ---------------------------------------------------------------------------
// 2) S = G * G^T  (8192 x 8192 x 512 fp32 SGEMM, 128x128x16 tiles)
// ---------------------------------------------------------------------------
__global__ __launch_bounds__(256) void gemm_gram_kernel() {
    __shared__ float As[16][128];
    __shared__ float Bs[16][128];
    int bx = blockIdx.x, by = blockIdx.y;
    int tid = threadIdx.x;
    int tx = tid & 15, ty = tid >> 4;
    const float* A = g_G + (size_t)by * 128 * D;
    const float* B = g_G + (size_t)bx * 128 * D;
    float acc[8][8];
#pragma unroll
    for (int i = 0; i < 8; i++)
#pragma unroll
        for (int j = 0; j < 8; j++) acc[i][j] = 0.0f;

    for (int k0 = 0; k0 < D; k0 += 16) {
#pragma unroll
        for (int i = 0; i < 2; i++) {
            int id  = tid + i * 256;       // 0..511
            int row = id >> 2;             // 0..127
            int kk  = (id & 3) << 2;       // 0,4,8,12
            float4 va = *(const float4*)(A + (size_t)row * D + k0 + kk);
            As[kk + 0][row] = va.x; As[kk + 1][row] = va.y;
            As[kk + 2][row] = va.z; As[kk + 3][row] = va.w;
            float4 vb = *(const float4*)(B + (size_t)row * D + k0 + kk);
            Bs[kk + 0][row] = vb.x; Bs[kk + 1][row] = vb.y;
            Bs[kk + 2][row] = vb.z; Bs[kk + 3][row] = vb.w;
        }
        __syncthreads();
#pragma unroll
        for (int k = 0; k < 16; k++) {
            float ra[8], rb[8];
#pragma unroll
            for (int i = 0; i < 8; i++) ra[i] = As[k][ty * 8 + i];
#pragma unroll
            for (int j = 0; j < 8; j++) rb[j] = Bs[k][tx * 8 + j];
#pragma unroll
            for (int i = 0; i < 8; i++)
#pragma unroll
                for (int j = 0; j < 8; j++) acc[i][j] += ra[i] * rb[j];
        }
        __syncthreads();
    }
#pragma unroll
    for (int i = 0; i < 8; i++) {
        size_t r = (size_t)(by * 128 + ty * 8 + i) * TWO_N + bx * 128 + tx * 8;
        *(float4*)(g_S + r)     = make_float4(acc[i][0], acc[i][1], acc[i][2], acc[i][3]);
        *(float4*)(g_S + r + 4) = make_float4(acc[i][4], acc[i][5], acc[i][6], acc[i][7]);
    }
}

// ---------------------------------------------------------------------------
// 3) Per-row radix select + middle exp-sum
// ---------------------------------------------------------------------------
__device__ __forceinline__ uint32_t f2k(float f) {
    uint32_t u = __float_as_uint(f);
    return (u & 0x80000000u) ? ~u : (u | 0x80000000u);
}
__device__ __forceinline__ float k2f(uint32_t u) {
    u = (u & 0x80000000u) ? (u & 0x7FFFFFFFu) : ~u;
    return __uint_as_float(u);
}

// kth largest (1-indexed) over keys[0..8191] in shared. blockDim = 256.
__device__ uint32_t select_kth_largest(const uint32_t* keys, uint32_t* hist,
                                       uint32_t* bcast, int k, int tid) {
    uint32_t prefix = 0, mask = 0;
    for (int shift = 24; shift >= 0; shift -= 8) {
        hist[tid] = 0;            // 256 threads == 256 bins
        __syncthreads();
        for (int i = tid; i < TWO_N; i += 256) {
            uint32_t u = keys[i];
            bool ok = (u & mask) == prefix;
            uint32_t d = ok ? ((u >> shift) & 255u) : 0xFFFFFFFFu;
            unsigned mm = __match_any_sync(0xFFFFFFFFu, d);
            if (ok && ((__ffs(mm) - 1) == (tid & 31)))
                atomicAdd(&hist[d], (uint32_t)__popc(mm));
        }
        __syncthreads();
        if (tid == 0) {
            int cum = 0, d = 255;
            for (; d >= 0; d--) { cum += (int)hist[d]; if (cum >= k) break; }
            bcast[0] = (uint32_t)d;
            bcast[1] = (uint32_t)(k - (cum - (int)hist[d]));
        }
        __syncthreads();
        prefix |= bcast[0] << shift;
        mask   |= 0xFFu << shift;
        k = (int)bcast[1];
        __syncthreads();
    }
    return prefix;
}

__global__ __launch_bounds__(256) void row_select_kernel(const float* __restrict__ tau_ptr) {
    extern __shared__ uint32_t sh[];
    uint32_t* keys = sh;             // 8192
    uint32_t* hist = sh + TWO_N;     // 256
    __shared__ uint32_t bcast[2];
    __shared__ float fred[8];
    __shared__ int   ired[16];
    int row = blockIdx.x, tid = threadIdx.x;
    const float* rp = g_S + (size_t)row * TWO_N;
    for (int i = tid; i < TWO_N; i += 256) keys[i] = f2k(rp[i]);
    __syncthreads();

    uint32_t vhi = select_kth_largest(keys, hist, bcast, T_DROP, tid);
    uint32_t vlo = select_kth_largest(keys, hist, bcast, TWO_N - T_DROP + 1, tid);

    float invtau = 1.0f / *tau_ptr;
    float sum = 0.0f;
    int cge = 0, cle = 0;
    for (int i = tid; i < TWO_N; i += 256) {
        uint32_t u = keys[i];
        if (u >= vhi)      cge++;
        else if (u <= vlo) cle++;
        else               sum += expf(k2f(u) * invtau);
    }
#pragma unroll
    for (int o = 16; o; o >>= 1) {
        sum += __shfl_xor_sync(0xffffffffu, sum, o);
        cge += __shfl_xor_sync(0xffffffffu, cge, o);
        cle += __shfl_xor_sync(0xffffffffu, cle, o);
    }
    if ((tid & 31) == 0) {
        fred[tid >> 5] = sum;
        ired[tid >> 5] = cge;
        ired[8 + (tid >> 5)] = cle;
    }
    __syncthreads();
    if (tid == 0) {
        float s = 0.0f; int g = 0, l = 0;
        for (int w = 0; w < 8; w++) { s += fred[w]; g += ired[w]; l += ired[8 + w]; }
        // tie-correction: keep duplicates of the threshold values beyond rank t
        s += (float)(g - T_DROP) * expf(k2f(vhi) * invtau)
           + (float)(l - T_DROP) * expf(k2f(vlo) * invtau);
        g_rowlog[row] = logf(s);
    }
}

// ---------------------------------------------------------------------------
// 4) Final reduction: mean_i [ 0.5*(log n1 + log n2) - s12[i,i]/tau ]
// ---------------------------------------------------------------------------
__global__ void final_kernel(const float* __restrict__ tau_ptr, float* __restrict__ out) {
    int tid = threadIdx.x;  // 256
    double invtau = 1.0 / (double)(*tau_ptr);
    double acc = 0.0;
    for (int i = tid; i < N_ROWS; i += 256) {
        float diag = g_S[(size_t)i * TWO_N + N_ROWS + i];
        acc += 0.5 * ((double)g_rowlog[i] + (double)g_rowlog[N_ROWS + i])
             - (double)diag * invtau;
    }
#pragma unroll
    for (int o = 16; o; o >>= 1) acc += __shfl_xor_sync(0xffffffffu, acc, o);
    __shared__ double dred[8];
    if ((tid & 31) == 0) dred[tid >> 5] = acc;
    __syncthreads();
    if (tid == 0) {
        double s = 0.0;
        for (int w = 0; w < 8; w++) s += dred[w];
        out[0] = (float)(s / (double)N_ROWS);
    }
}

// ---------------------------------------------------------------------------
extern "C" void kernel_launch(void* const* d_in, const int* in_sizes, int n_in,
                              void* d_out, int out_size) {
    const float* h1  = (const float*)d_in[0];
    const float* h2  = (const float*)d_in[1];
    // d_in[2] = y (int64) — unused by the reference loss
    const float* tau = (const float*)d_in[3];
    float* out = (float*)d_out;

    normalize_kernel<<<TWO_N, 128>>>(h1, h2);
    dim3 gg(TWO_N / 128, TWO_N / 128);
    gemm_gram_kernel<<<gg, 256>>>();
    size_t smem = (size_t)(TWO_N + 256) * sizeof(uint32_t);
    row_select_kernel<<<TWO_N, 256, smem>>>(tau);
    final_kernel<<<1, 256>>>(tau, out);
}

// round 5
// speedup vs baseline: 4.2590x; 4.2590x over previous
#include <cuda_runtime.h>
#include <cuda_fp16.h>
#include <cuda_bf16.h>
#include <cstdint>
#include <cstddef>

#define N_ROWS 4096
#define D 512
#define TWO_N 8192
#define T_DROP 409
#define CHUNKS 8              // 512 / 64 K-elems per chunk
#define PANEL_BYTES 16384     // 128 rows x 128 bytes (64 bf16)

// ---------------- device scratch (allocation-free rule) ----------------
__device__ __align__(1024) uint16_t g_Gp[(size_t)TWO_N * D];      // bf16 SW128 panels (8 MB)
__device__ __align__(16)   uint16_t g_S16[(size_t)TWO_N * TWO_N]; // fp16 Gram (128 MB)
__device__ float g_rowlog[TWO_N];

// ---------------- PTX helpers ----------------
__device__ __forceinline__ uint32_t smem_u32(const void* p) {
    uint32_t a;
    asm("{ .reg .u64 t; cvta.to.shared.u64 t, %1; cvt.u32.u64 %0, t; }" : "=r"(a) : "l"(p));
    return a;
}
__device__ __forceinline__ void cp16(uint32_t saddr, const void* g) {
    asm volatile("cp.async.cg.shared.global [%0], [%1], 16;" :: "r"(saddr), "l"(g));
}
__device__ __forceinline__ void cp_commit() {
    asm volatile("cp.async.commit_group;" ::: "memory");
}
template <int N> __device__ __forceinline__ void cp_wait() {
    asm volatile("cp.async.wait_group %0;" :: "n"(N) : "memory");
}
__device__ __forceinline__ void ldsm4(uint32_t* r, uint32_t addr) {
    asm volatile("ldmatrix.sync.aligned.m8n8.x4.shared.b16 {%0,%1,%2,%3}, [%4];"
                 : "=r"(r[0]), "=r"(r[1]), "=r"(r[2]), "=r"(r[3]) : "r"(addr));
}
__device__ __forceinline__ void mma16816(float* d, const uint32_t* a, const uint32_t* b) {
    asm volatile(
        "mma.sync.aligned.m16n8k16.row.col.f32.bf16.bf16.f32 "
        "{%0,%1,%2,%3}, {%4,%5,%6,%7}, {%8,%9}, {%0,%1,%2,%3};"
        : "+f"(d[0]), "+f"(d[1]), "+f"(d[2]), "+f"(d[3])
        : "r"(a[0]), "r"(a[1]), "r"(a[2]), "r"(a[3]), "r"(b[0]), "r"(b[1]));
}
__device__ __forceinline__ uint32_t swz128(uint32_t off) { return off ^ ((off >> 3) & 0x70); }

// ---------------------------------------------------------------------------
// 1) Row L2-normalize into bf16 SW128-swizzled panels.
// ---------------------------------------------------------------------------
__global__ __launch_bounds__(128) void normalize_kernel(const float* __restrict__ h1,
                                                        const float* __restrict__ h2) {
    int half_ = threadIdx.x >> 6;
    int g     = threadIdx.x & 63;
    int row   = blockIdx.x * 2 + half_;
    const float* src = (row < N_ROWS) ? (h1 + (size_t)row * D)
                                      : (h2 + (size_t)(row - N_ROWS) * D);
    float4 v0 = ((const float4*)src)[g * 2];
    float4 v1 = ((const float4*)src)[g * 2 + 1];
    float ss = v0.x * v0.x + v0.y * v0.y + v0.z * v0.z + v0.w * v0.w
             + v1.x * v1.x + v1.y * v1.y + v1.z * v1.z + v1.w * v1.w;
#pragma unroll
    for (int o = 16; o; o >>= 1) ss += __shfl_xor_sync(0xffffffffu, ss, o);
    __shared__ float ws[4];
    if ((threadIdx.x & 31) == 0) ws[threadIdx.x >> 5] = ss;
    __syncthreads();
    float tot = ws[half_ * 2] + ws[half_ * 2 + 1];
    float inv = 1.0f / fmaxf(sqrtf(tot), 1e-12f);

    __nv_bfloat162 b0 = __floats2bfloat162_rn(v0.x * inv, v0.y * inv);
    __nv_bfloat162 b1 = __floats2bfloat162_rn(v0.z * inv, v0.w * inv);
    __nv_bfloat162 b2 = __floats2bfloat162_rn(v1.x * inv, v1.y * inv);
    __nv_bfloat162 b3 = __floats2bfloat162_rn(v1.z * inv, v1.w * inv);
    uint4 w;
    w.x = *reinterpret_cast<uint32_t*>(&b0);
    w.y = *reinterpret_cast<uint32_t*>(&b1);
    w.z = *reinterpret_cast<uint32_t*>(&b2);
    w.w = *reinterpret_cast<uint32_t*>(&b3);

    int kc = g >> 3, gi = g & 7;
    size_t panel = ((size_t)(row >> 7) * CHUNKS + kc) * PANEL_BYTES;
    uint32_t off = swz128((uint32_t)(row & 127) * 128 + gi * 16);
    *reinterpret_cast<uint4*>(reinterpret_cast<char*>(g_Gp) + panel + off) = w;
}

// ---------------------------------------------------------------------------
// 2) S = G*G^T via mma.sync bf16 (128x128 tiles, symmetric: bx >= by only).
// ---------------------------------------------------------------------------
#define SMEM_GEMM 65536
#define STAGE_LD 130   // fp16 stage tile row stride (conflict-free transpose reads)

__global__ __launch_bounds__(256) void gram_mma_kernel() {
    extern __shared__ __align__(1024) char smc[];
    int bx = blockIdx.x, by = blockIdx.y;
    if (bx < by) return;

    uint32_t sb = smem_u32(smc);
    int tid = threadIdx.x, wid = tid >> 5, lane = tid & 31;
    int mOff = (wid & 3) * 32;     // warp M offset in tile
    int nOff = (wid >> 2) * 64;    // warp N offset in tile

    const char* Ap = reinterpret_cast<const char*>(g_Gp) + (size_t)by * CHUNKS * PANEL_BYTES;
    const char* Bp = reinterpret_cast<const char*>(g_Gp) + (size_t)bx * CHUNKS * PANEL_BYTES;

    auto copy_chunk = [&](int c, int buf) {
        uint32_t sA = sb + buf * 16384;
        uint32_t sB = sb + 32768 + buf * 16384;
        const char* gA = Ap + (size_t)c * PANEL_BYTES;
        const char* gB = Bp + (size_t)c * PANEL_BYTES;
#pragma unroll
        for (int i = 0; i < 4; i++) cp16(sA + (tid + i * 256) * 16, gA + (tid + i * 256) * 16);
#pragma unroll
        for (int i = 0; i < 4; i++) cp16(sB + (tid + i * 256) * 16, gB + (tid + i * 256) * 16);
        cp_commit();
    };

    // Per-lane ldmatrix address components (SW128: XOR = (row&7)*16, 16B granular)
    uint32_t offA[2], xorA[2];
#pragma unroll
    for (int mt = 0; mt < 2; mt++) {
        uint32_t r = mOff + mt * 16 + (lane & 15);
        offA[mt] = r * 128; xorA[mt] = (r & 7) * 16;
    }
    uint32_t colA = (lane >> 4) * 16;
    uint32_t offB[4], xorB[4];
#pragma unroll
    for (int nb = 0; nb < 4; nb++) {
        uint32_t r = nOff + nb * 16 + (lane & 7) + ((lane >> 4) << 3);
        offB[nb] = r * 128; xorB[nb] = (r & 7) * 16;
    }
    uint32_t colB = ((lane >> 3) & 1) * 16;

    float acc[2][8][4];
#pragma unroll
    for (int i = 0; i < 2; i++)
#pragma unroll
        for (int j = 0; j < 8; j++)
#pragma unroll
            for (int k = 0; k < 4; k++) acc[i][j][k] = 0.0f;

    copy_chunk(0, 0);
    copy_chunk(1, 1);

    for (int c = 0; c < CHUNKS; c++) {
        int buf = c & 1;
        if (c < CHUNKS - 1) cp_wait<1>(); else cp_wait<0>();
        __syncthreads();
        uint32_t sA = sb + buf * 16384;
        uint32_t sB = sb + 32768 + buf * 16384;
#pragma unroll
        for (int ks = 0; ks < 4; ks++) {
            uint32_t a[2][4], b[4][4];
#pragma unroll
            for (int mt = 0; mt < 2; mt++)
                ldsm4(a[mt], sA + offA[mt] + (((uint32_t)ks * 32 + colA) ^ xorA[mt]));
#pragma unroll
            for (int nb = 0; nb < 4; nb++)
                ldsm4(b[nb], sB + offB[nb] + (((uint32_t)ks * 32 + colB) ^ xorB[nb]));
#pragma unroll
            for (int mt = 0; mt < 2; mt++)
#pragma unroll
                for (int nb = 0; nb < 4; nb++) {
                    mma16816(acc[mt][nb * 2],     a[mt], &b[nb][0]);
                    mma16816(acc[mt][nb * 2 + 1], a[mt], &b[nb][2]);
                }
        }
        __syncthreads();
        if (c + 2 < CHUNKS) copy_chunk(c + 2, buf);
    }

    // ---- Epilogue: stage fp16 tile in smem, write tile (+ mirror) coalesced ----
    __half* st = reinterpret_cast<__half*>(smc);
    int rr = lane >> 2, cc = (lane & 3) * 2;
#pragma unroll
    for (int mt = 0; mt < 2; mt++)
#pragma unroll
        for (int nt = 0; nt < 8; nt++) {
            int r = mOff + mt * 16 + rr;
            int ccol = nOff + nt * 8 + cc;
            __half2 lo = __floats2half2_rn(acc[mt][nt][0], acc[mt][nt][1]);
            __half2 hi = __floats2half2_rn(acc[mt][nt][2], acc[mt][nt][3]);
            *reinterpret_cast<__half2*>(&st[r * STAGE_LD + ccol]) = lo;
            *reinterpret_cast<__half2*>(&st[(r + 8) * STAGE_LD + ccol]) = hi;
        }
    __syncthreads();

    // direct tile: row-major coalesced
    for (int i = tid; i < 128 * 64; i += 256) {
        int r = i >> 6, cw = i & 63;
        uint32_t v = *reinterpret_cast<uint32_t*>(&st[r * STAGE_LD + cw * 2]);
        *reinterpret_cast<uint32_t*>(&g_S16[(size_t)(by * 128 + r) * TWO_N + bx * 128 + cw * 2]) = v;
    }
    if (bx > by) {
        // mirror: out[c][r] = tile[r][c]
        for (int i = tid; i < 128 * 64; i += 256) {
            int c = i >> 6, rw = i & 63;
            __half lo = st[(2 * rw) * STAGE_LD + c];
            __half hi = st[(2 * rw + 1) * STAGE_LD + c];
            __half2 v = __halves2half2(lo, hi);
            *reinterpret_cast<__half2*>(&g_S16[(size_t)(bx * 128 + c) * TWO_N + by * 128 + 2 * rw]) = v;
        }
    }
}

// ---------------------------------------------------------------------------
// 3) Per-row 16-bit radix select + exp-sum
// ---------------------------------------------------------------------------
__device__ __forceinline__ uint32_t f2k16(uint32_t u16) {
    return (u16 & 0x8000u) ? (uint32_t)((~u16) & 0xFFFFu) : (u16 | 0x8000u);
}
__device__ __forceinline__ float k2f16(uint32_t k) {
    uint32_t u = (k & 0x8000u) ? (k & 0x7FFFu) : ((~k) & 0xFFFFu);
    return __half2float(__ushort_as_half((unsigned short)u));
}

__global__ __launch_bounds__(256) void row_select_kernel(const float* __restrict__ tau_ptr) {
    __shared__ uint32_t keys32[TWO_N / 2];
    __shared__ uint32_t histA[256], histB[256];
    __shared__ uint32_t bc[8];
    __shared__ float fred[8];
    __shared__ int   ired[16];
    int row = blockIdx.x, tid = threadIdx.x;
    const uint32_t* rp = reinterpret_cast<const uint32_t*>(g_S16 + (size_t)row * TWO_N);

    histA[tid] = 0;
    for (int i = tid; i < TWO_N / 2; i += 256) {
        uint32_t w = rp[i];
        keys32[i] = f2k16(w & 0xFFFFu) | (f2k16(w >> 16) << 16);
    }
    __syncthreads();

    for (int i = tid; i < TWO_N / 2; i += 256) {
        uint32_t w = keys32[i];
        uint32_t d0 = (w >> 8) & 0xFFu, d1 = w >> 24;
        unsigned m0 = __match_any_sync(0xffffffffu, d0);
        if ((__ffs(m0) - 1) == (tid & 31)) atomicAdd(&histA[d0], (uint32_t)__popc(m0));
        unsigned m1 = __match_any_sync(0xffffffffu, d1);
        if ((__ffs(m1) - 1) == (tid & 31)) atomicAdd(&histA[d1], (uint32_t)__popc(m1));
    }
    __syncthreads();
    if (tid == 0) {
        int cum = 0, dhi = -1, dlo = -1, khi = 0, klo = 0;
        const int KLO = TWO_N - T_DROP + 1;
        for (int d = 255; d >= 0; d--) {
            int h = (int)histA[d]; cum += h;
            if (dhi < 0 && cum >= T_DROP) { dhi = d; khi = T_DROP - (cum - h); }
            if (dlo < 0 && cum >= KLO)    { dlo = d; klo = KLO - (cum - h); break; }
        }
        bc[0] = (uint32_t)dhi; bc[1] = (uint32_t)khi;
        bc[2] = (uint32_t)dlo; bc[3] = (uint32_t)klo;
    }
    __syncthreads();
    uint32_t dhi = bc[0], khi = bc[1], dlo = bc[2], klo = bc[3];
    histA[tid] = 0; histB[tid] = 0;
    __syncthreads();

    for (int i = tid; i < TWO_N / 2; i += 256) {
        uint32_t w = keys32[i];
        uint32_t k0 = w & 0xFFFFu, k1 = w >> 16;
        if ((k0 >> 8) == dhi) atomicAdd(&histA[k0 & 0xFFu], 1u);
        if ((k0 >> 8) == dlo) atomicAdd(&histB[k0 & 0xFFu], 1u);
        if ((k1 >> 8) == dhi) atomicAdd(&histA[k1 & 0xFFu], 1u);
        if ((k1 >> 8) == dlo) atomicAdd(&histB[k1 & 0xFFu], 1u);
    }
    __syncthreads();
    if (tid == 0) {
        int cum = 0;
        for (int d = 255; d >= 0; d--) { cum += (int)histA[d]; if (cum >= (int)khi) { bc[4] = (dhi << 8) | (uint32_t)d; break; } }
        cum = 0;
        for (int d = 255; d >= 0; d--) { cum += (int)histB[d]; if (cum >= (int)klo) { bc[5] = (dlo << 8) | (uint32_t)d; break; } }
    }
    __syncthreads();
    uint32_t vhi = bc[4], vlo = bc[5];

    float invtau = 1.0f / *tau_ptr;
    float sum = 0.0f;
    int cge = 0, cle = 0;
    for (int i = tid; i < TWO_N / 2; i += 256) {
        uint32_t w = keys32[i];
#pragma unroll
        for (int hh = 0; hh < 2; hh++) {
            uint32_t u = (hh == 0) ? (w & 0xFFFFu) : (w >> 16);
            if (u >= vhi)      cge++;
            else if (u <= vlo) cle++;
            else               sum += expf(k2f16(u) * invtau);
        }
    }
#pragma unroll
    for (int o = 16; o; o >>= 1) {
        sum += __shfl_xor_sync(0xffffffffu, sum, o);
        cge += __shfl_xor_sync(0xffffffffu, cge, o);
        cle += __shfl_xor_sync(0xffffffffu, cle, o);
    }
    if ((tid & 31) == 0) { fred[tid >> 5] = sum; ired[tid >> 5] = cge; ired[8 + (tid >> 5)] = cle; }
    __syncthreads();
    if (tid == 0) {
        float s = 0.0f; int g = 0, l = 0;
        for (int w = 0; w < 8; w++) { s += fred[w]; g += ired[w]; l += ired[8 + w]; }
        s += (float)(g - T_DROP) * expf(k2f16(vhi) * invtau)
           + (float)(l - T_DROP) * expf(k2f16(vlo) * invtau);
        g_rowlog[row] = logf(s);
    }
}

// ---------------------------------------------------------------------------
// 4) Final reduction
// ---------------------------------------------------------------------------
__global__ void final_kernel(const float* __restrict__ tau_ptr, float* __restrict__ out) {
    int tid = threadIdx.x;
    double invtau = 1.0 / (double)(*tau_ptr);
    double acc = 0.0;
    for (int i = tid; i < N_ROWS; i += 256) {
        float diag = __half2float(reinterpret_cast<const __half*>(g_S16)[(size_t)i * TWO_N + N_ROWS + i]);
        acc += 0.5 * ((double)g_rowlog[i] + (double)g_rowlog[N_ROWS + i]) - (double)diag * invtau;
    }
#pragma unroll
    for (int o = 16; o; o >>= 1) acc += __shfl_xor_sync(0xffffffffu, acc, o);
    __shared__ double dred[8];
    if ((tid & 31) == 0) dred[tid >> 5] = acc;
    __syncthreads();
    if (tid == 0) {
        double s = 0.0;
        for (int w = 0; w < 8; w++) s += dred[w];
        out[0] = (float)(s / (double)N_ROWS);
    }
}

// ---------------------------------------------------------------------------
extern "C" void kernel_launch(void* const* d_in, const int* in_sizes, int n_in,
                              void* d_out, int out_size) {
    const float* h1  = (const float*)d_in[0];
    const float* h2  = (const float*)d_in[1];
    const float* tau = (const float*)d_in[3];
    float* out = (float*)d_out;

    cudaFuncSetAttribute(gram_mma_kernel, cudaFuncAttributeMaxDynamicSharedMemorySize, SMEM_GEMM);

    normalize_kernel<<<TWO_N / 2, 128>>>(h1, h2);
    gram_mma_kernel<<<dim3(64, 64), 256, SMEM_GEMM>>>();
    row_select_kernel<<<TWO_N, 256>>>(tau);
    final_kernel<<<1, 256>>>(tau, out);
}

// round 6
// speedup vs baseline: 4.9391x; 1.1597x over previous
#include <cuda_runtime.h>
#include <cuda_fp16.h>
#include <cuda_bf16.h>
#include <cstdint>
#include <cstddef>

#define N_ROWS 4096
#define D 512
#define TWO_N 8192
#define T_DROP 409
#define CHUNKS 8              // 512 / 64 K-elems per chunk
#define PANEL_BYTES 16384     // 128 rows x 128 bytes (64 bf16)

// ---------------- device scratch (allocation-free rule) ----------------
__device__ __align__(1024) uint16_t g_Gp[(size_t)TWO_N * D];      // bf16 SW128 panels (8 MB)
__device__ __align__(16)   uint16_t g_S16[(size_t)TWO_N * TWO_N]; // fp16 Gram (128 MB)
__device__ float g_rowlog[TWO_N];
__device__ float g_diag[N_ROWS];                                  // S[i, 4096+i]

// ---------------- PTX helpers ----------------
__device__ __forceinline__ uint32_t smem_u32(const void* p) {
    uint32_t a;
    asm("{ .reg .u64 t; cvta.to.shared.u64 t, %1; cvt.u32.u64 %0, t; }" : "=r"(a) : "l"(p));
    return a;
}
__device__ __forceinline__ void cp16(uint32_t saddr, const void* g) {
    asm volatile("cp.async.cg.shared.global [%0], [%1], 16;" :: "r"(saddr), "l"(g));
}
__device__ __forceinline__ void cp_commit() {
    asm volatile("cp.async.commit_group;" ::: "memory");
}
template <int N> __device__ __forceinline__ void cp_wait() {
    asm volatile("cp.async.wait_group %0;" :: "n"(N) : "memory");
}
__device__ __forceinline__ void ldsm4(uint32_t* r, uint32_t addr) {
    asm volatile("ldmatrix.sync.aligned.m8n8.x4.shared.b16 {%0,%1,%2,%3}, [%4];"
                 : "=r"(r[0]), "=r"(r[1]), "=r"(r[2]), "=r"(r[3]) : "r"(addr));
}
__device__ __forceinline__ void mma16816(float* d, const uint32_t* a, const uint32_t* b) {
    asm volatile(
        "mma.sync.aligned.m16n8k16.row.col.f32.bf16.bf16.f32 "
        "{%0,%1,%2,%3}, {%4,%5,%6,%7}, {%8,%9}, {%0,%1,%2,%3};"
        : "+f"(d[0]), "+f"(d[1]), "+f"(d[2]), "+f"(d[3])
        : "r"(a[0]), "r"(a[1]), "r"(a[2]), "r"(a[3]), "r"(b[0]), "r"(b[1]));
}
__device__ __forceinline__ uint32_t swz128(uint32_t off) { return off ^ ((off >> 3) & 0x70); }

// ---------------------------------------------------------------------------
// 1) Row L2-normalize into bf16 SW128-swizzled panels.
// ---------------------------------------------------------------------------
__global__ __launch_bounds__(128) void normalize_kernel(const float* __restrict__ h1,
                                                        const float* __restrict__ h2) {
    int half_ = threadIdx.x >> 6;
    int g     = threadIdx.x & 63;
    int row   = blockIdx.x * 2 + half_;
    const float* src = (row < N_ROWS) ? (h1 + (size_t)row * D)
                                      : (h2 + (size_t)(row - N_ROWS) * D);
    float4 v0 = ((const float4*)src)[g * 2];
    float4 v1 = ((const float4*)src)[g * 2 + 1];
    float ss = v0.x * v0.x + v0.y * v0.y + v0.z * v0.z + v0.w * v0.w
             + v1.x * v1.x + v1.y * v1.y + v1.z * v1.z + v1.w * v1.w;
#pragma unroll
    for (int o = 16; o; o >>= 1) ss += __shfl_xor_sync(0xffffffffu, ss, o);
    __shared__ float ws[4];
    if ((threadIdx.x & 31) == 0) ws[threadIdx.x >> 5] = ss;
    __syncthreads();
    float tot = ws[half_ * 2] + ws[half_ * 2 + 1];
    float inv = 1.0f / fmaxf(sqrtf(tot), 1e-12f);

    __nv_bfloat162 b0 = __floats2bfloat162_rn(v0.x * inv, v0.y * inv);
    __nv_bfloat162 b1 = __floats2bfloat162_rn(v0.z * inv, v0.w * inv);
    __nv_bfloat162 b2 = __floats2bfloat162_rn(v1.x * inv, v1.y * inv);
    __nv_bfloat162 b3 = __floats2bfloat162_rn(v1.z * inv, v1.w * inv);
    uint4 w;
    w.x = *reinterpret_cast<uint32_t*>(&b0);
    w.y = *reinterpret_cast<uint32_t*>(&b1);
    w.z = *reinterpret_cast<uint32_t*>(&b2);
    w.w = *reinterpret_cast<uint32_t*>(&b3);

    int kc = g >> 3, gi = g & 7;
    size_t panel = ((size_t)(row >> 7) * CHUNKS + kc) * PANEL_BYTES;
    uint32_t off = swz128((uint32_t)(row & 127) * 128 + gi * 16);
    *reinterpret_cast<uint4*>(reinterpret_cast<char*>(g_Gp) + panel + off) = w;
}

// ---------------------------------------------------------------------------
// 2) S = G*G^T via mma.sync bf16 (128x128 tiles, symmetric: bx >= by only).
// ---------------------------------------------------------------------------
#define SMEM_GEMM 65536
#define STAGE_LD 130   // fp16 stage tile row stride (conflict-free transpose reads)

__global__ __launch_bounds__(256) void gram_mma_kernel() {
    extern __shared__ __align__(1024) char smc[];
    int bx = blockIdx.x, by = blockIdx.y;
    if (bx < by) return;

    uint32_t sb = smem_u32(smc);
    int tid = threadIdx.x, wid = tid >> 5, lane = tid & 31;
    int mOff = (wid & 3) * 32;     // warp M offset in tile
    int nOff = (wid >> 2) * 64;    // warp N offset in tile

    const char* Ap = reinterpret_cast<const char*>(g_Gp) + (size_t)by * CHUNKS * PANEL_BYTES;
    const char* Bp = reinterpret_cast<const char*>(g_Gp) + (size_t)bx * CHUNKS * PANEL_BYTES;

    auto copy_chunk = [&](int c, int buf) {
        uint32_t sA = sb + buf * 16384;
        uint32_t sB = sb + 32768 + buf * 16384;
        const char* gA = Ap + (size_t)c * PANEL_BYTES;
        const char* gB = Bp + (size_t)c * PANEL_BYTES;
#pragma unroll
        for (int i = 0; i < 4; i++) cp16(sA + (tid + i * 256) * 16, gA + (tid + i * 256) * 16);
#pragma unroll
        for (int i = 0; i < 4; i++) cp16(sB + (tid + i * 256) * 16, gB + (tid + i * 256) * 16);
        cp_commit();
    };

    // Per-lane ldmatrix address components (SW128: XOR = (row&7)*16, 16B granular)
    uint32_t offA[2], xorA[2];
#pragma unroll
    for (int mt = 0; mt < 2; mt++) {
        uint32_t r = mOff + mt * 16 + (lane & 15);
        offA[mt] = r * 128; xorA[mt] = (r & 7) * 16;
    }
    uint32_t colA = (lane >> 4) * 16;
    uint32_t offB[4], xorB[4];
#pragma unroll
    for (int nb = 0; nb < 4; nb++) {
        uint32_t r = nOff + nb * 16 + (lane & 7) + ((lane >> 4) << 3);
        offB[nb] = r * 128; xorB[nb] = (r & 7) * 16;
    }
    uint32_t colB = ((lane >> 3) & 1) * 16;

    float acc[2][8][4];
#pragma unroll
    for (int i = 0; i < 2; i++)
#pragma unroll
        for (int j = 0; j < 8; j++)
#pragma unroll
            for (int k = 0; k < 4; k++) acc[i][j][k] = 0.0f;

    copy_chunk(0, 0);
    copy_chunk(1, 1);

    for (int c = 0; c < CHUNKS; c++) {
        int buf = c & 1;
        if (c < CHUNKS - 1) cp_wait<1>(); else cp_wait<0>();
        __syncthreads();
        uint32_t sA = sb + buf * 16384;
        uint32_t sB = sb + 32768 + buf * 16384;
#pragma unroll
        for (int ks = 0; ks < 4; ks++) {
            uint32_t a[2][4], b[4][4];
#pragma unroll
            for (int mt = 0; mt < 2; mt++)
                ldsm4(a[mt], sA + offA[mt] + (((uint32_t)ks * 32 + colA) ^ xorA[mt]));
#pragma unroll
            for (int nb = 0; nb < 4; nb++)
                ldsm4(b[nb], sB + offB[nb] + (((uint32_t)ks * 32 + colB) ^ xorB[nb]));
#pragma unroll
            for (int mt = 0; mt < 2; mt++)
#pragma unroll
                for (int nb = 0; nb < 4; nb++) {
                    mma16816(acc[mt][nb * 2],     a[mt], &b[nb][0]);
                    mma16816(acc[mt][nb * 2 + 1], a[mt], &b[nb][2]);
                }
        }
        __syncthreads();
        if (c + 2 < CHUNKS) copy_chunk(c + 2, buf);
    }

    // ---- Epilogue: stage fp16 tile in smem, write tile (+ mirror) coalesced ----
    __half* st = reinterpret_cast<__half*>(smc);
    int rr = lane >> 2, cc = (lane & 3) * 2;
#pragma unroll
    for (int mt = 0; mt < 2; mt++)
#pragma unroll
        for (int nt = 0; nt < 8; nt++) {
            int r = mOff + mt * 16 + rr;
            int ccol = nOff + nt * 8 + cc;
            __half2 lo = __floats2half2_rn(acc[mt][nt][0], acc[mt][nt][1]);
            __half2 hi = __floats2half2_rn(acc[mt][nt][2], acc[mt][nt][3]);
            *reinterpret_cast<__half2*>(&st[r * STAGE_LD + ccol]) = lo;
            *reinterpret_cast<__half2*>(&st[(r + 8) * STAGE_LD + ccol]) = hi;
        }
    __syncthreads();

    // diag of s12: tile (by, bx=by+32) holds S[by*128+r][4096+by*128+r] at st[r][r]
    if (bx == by + 32) {
        for (int i = tid; i < 128; i += 256)
            g_diag[by * 128 + i] = __half2float(st[i * STAGE_LD + i]);
    }

    // direct tile: row-major coalesced
    for (int i = tid; i < 128 * 64; i += 256) {
        int r = i >> 6, cw = i & 63;
        uint32_t v = *reinterpret_cast<uint32_t*>(&st[r * STAGE_LD + cw * 2]);
        *reinterpret_cast<uint32_t*>(&g_S16[(size_t)(by * 128 + r) * TWO_N + bx * 128 + cw * 2]) = v;
    }
    if (bx > by) {
        // mirror: out[c][r] = tile[r][c]
        for (int i = tid; i < 128 * 64; i += 256) {
            int c = i >> 6, rw = i & 63;
            __half lo = st[(2 * rw) * STAGE_LD + c];
            __half hi = st[(2 * rw + 1) * STAGE_LD + c];
            __half2 v = __halves2half2(lo, hi);
            *reinterpret_cast<__half2*>(&g_S16[(size_t)(bx * 128 + c) * TWO_N + by * 128 + 2 * rw]) = v;
        }
    }
}

// ---------------------------------------------------------------------------
// 3) Per-row 16-bit radix select + exp-sum (3 passes, vectorized)
// ---------------------------------------------------------------------------
// packed order-preserving key map for two fp16 halves:
//   per half: sign ? ~u : u|0x8000   ==   u ^ (0x8000 | (sign ? 0x7FFF : 0))
__device__ __forceinline__ uint32_t f2k16x2(uint32_t u) {
    uint32_t s = (u >> 15) & 0x00010001u;
    return u ^ (0x80008000u | (s * 0x7FFFu));
}
__device__ __forceinline__ float k2f16(uint32_t k) {
    uint32_t u = (k & 0x8000u) ? (k & 0x7FFFu) : ((~k) & 0xFFFFu);
    return __half2float(__ushort_as_half((unsigned short)u));
}
__device__ __forceinline__ void hist_add(uint32_t* h, uint32_t d, int lane) {
    unsigned m = __match_any_sync(0xffffffffu, d);
    if ((__ffs(m) - 1) == lane) atomicAdd(&h[d], (uint32_t)__popc(m));
}

__global__ __launch_bounds__(256) void row_select_kernel(const float* __restrict__ tau_ptr) {
    __shared__ __align__(16) uint32_t keys32[TWO_N / 2];   // 16 KB
    __shared__ uint32_t histT[256];                        // top-byte counts
    __shared__ uint32_t scanT[256];                        // suffix scan
    __shared__ uint32_t lowA[256], lowB[256];              // low-byte hists (candidate bins)
    __shared__ uint32_t bc[8];
    __shared__ float fred[8];
    __shared__ int   ired[16];
    int row = blockIdx.x, tid = threadIdx.x, lane = tid & 31;
    const uint4* rp4 = reinterpret_cast<const uint4*>(g_S16 + (size_t)row * TWO_N);

    histT[tid] = 0; lowA[tid] = 0; lowB[tid] = 0;
    __syncthreads();

    // ---- pass 0: load + convert + store + top-byte histogram (uint4 = 8 keys) ----
    for (int i = tid; i < TWO_N / 8; i += 256) {
        uint4 w = rp4[i];
        uint32_t k0 = f2k16x2(w.x), k1 = f2k16x2(w.y), k2 = f2k16x2(w.z), k3 = f2k16x2(w.w);
        reinterpret_cast<uint4*>(keys32)[i] = make_uint4(k0, k1, k2, k3);
        hist_add(histT, (k0 >> 8) & 255u, lane);  hist_add(histT, k0 >> 24, lane);
        hist_add(histT, (k1 >> 8) & 255u, lane);  hist_add(histT, k1 >> 24, lane);
        hist_add(histT, (k2 >> 8) & 255u, lane);  hist_add(histT, k2 >> 24, lane);
        hist_add(histT, (k3 >> 8) & 255u, lane);  hist_add(histT, k3 >> 24, lane);
    }
    __syncthreads();

    // ---- pass 1: parallel suffix-scan over 256 bins; unique thread fires per k ----
    scanT[tid] = histT[tid];
    __syncthreads();
#pragma unroll
    for (int stp = 1; stp < 256; stp <<= 1) {
        uint32_t v = scanT[tid] + ((tid + stp < 256) ? scanT[tid + stp] : 0u);
        __syncthreads();
        scanT[tid] = v;
        __syncthreads();
    }
    {
        const uint32_t KLO = TWO_N - T_DROP + 1;
        uint32_t mine = scanT[tid];
        uint32_t nxt  = (tid < 255) ? scanT[tid + 1] : 0u;
        if (mine >= T_DROP && nxt < T_DROP) { bc[0] = (uint32_t)tid; bc[1] = T_DROP - nxt; }
        if (mine >= KLO    && nxt < KLO)    { bc[2] = (uint32_t)tid; bc[3] = KLO - nxt; }
    }
    __syncthreads();
    uint32_t dhi = bc[0], khi = bc[1], dlo = bc[2], klo = bc[3];

    // ---- pass 2: low-byte hists for the two candidate bins (rare hits) ----
    for (int i = tid; i < TWO_N / 8; i += 256) {
        uint4 w = reinterpret_cast<const uint4*>(keys32)[i];
#pragma unroll
        for (int j = 0; j < 4; j++) {
            uint32_t kk = (j == 0) ? w.x : (j == 1) ? w.y : (j == 2) ? w.z : w.w;
#pragma unroll
            for (int hh = 0; hh < 2; hh++) {
                uint32_t u = (hh == 0) ? (kk & 0xFFFFu) : (kk >> 16);
                uint32_t tb = u >> 8;
                if (tb == dhi) atomicAdd(&lowA[u & 0xFFu], 1u);
                if (tb == dlo) atomicAdd(&lowB[u & 0xFFu], 1u);
            }
        }
    }
    __syncthreads();
    // suffix-scan both low hists simultaneously (reuse scanT trick in two arrays)
    scanT[tid] = lowA[tid];
    __syncthreads();
#pragma unroll
    for (int stp = 1; stp < 256; stp <<= 1) {
        uint32_t v = scanT[tid] + ((tid + stp < 256) ? scanT[tid + stp] : 0u);
        __syncthreads();
        scanT[tid] = v;
        __syncthreads();
    }
    {
        uint32_t mine = scanT[tid], nxt = (tid < 255) ? scanT[tid + 1] : 0u;
        if (mine >= khi && nxt < khi) bc[4] = (dhi << 8) | (uint32_t)tid;
    }
    __syncthreads();
    scanT[tid] = lowB[tid];
    __syncthreads();
#pragma unroll
    for (int stp = 1; stp < 256; stp <<= 1) {
        uint32_t v = scanT[tid] + ((tid + stp < 256) ? scanT[tid + stp] : 0u);
        __syncthreads();
        scanT[tid] = v;
        __syncthreads();
    }
    {
        uint32_t mine = scanT[tid], nxt = (tid < 255) ? scanT[tid + 1] : 0u;
        if (mine >= klo && nxt < klo) bc[5] = (dlo << 8) | (uint32_t)tid;
    }
    __syncthreads();
    uint32_t vhi = bc[4], vlo = bc[5];

    // ---- pass 3: strict-middle exp-sum + tie counts (hardware __expf) ----
    float invtau = 1.0f / *tau_ptr;
    float sum = 0.0f;
    int cge = 0, cle = 0;
    for (int i = tid; i < TWO_N / 8; i += 256) {
        uint4 w = reinterpret_cast<const uint4*>(keys32)[i];
#pragma unroll
        for (int j = 0; j < 4; j++) {
            uint32_t kk = (j == 0) ? w.x : (j == 1) ? w.y : (j == 2) ? w.z : w.w;
#pragma unroll
            for (int hh = 0; hh < 2; hh++) {
                uint32_t u = (hh == 0) ? (kk & 0xFFFFu) : (kk >> 16);
                if (u >= vhi)      cge++;
                else if (u <= vlo) cle++;
                else               sum += __expf(k2f16(u) * invtau);
            }
        }
    }
#pragma unroll
    for (int o = 16; o; o >>= 1) {
        sum += __shfl_xor_sync(0xffffffffu, sum, o);
        cge += __shfl_xor_sync(0xffffffffu, cge, o);
        cle += __shfl_xor_sync(0xffffffffu, cle, o);
    }
    if ((tid & 31) == 0) { fred[tid >> 5] = sum; ired[tid >> 5] = cge; ired[8 + (tid >> 5)] = cle; }
    __syncthreads();
    if (tid == 0) {
        float s = 0.0f; int g = 0, l = 0;
        for (int w = 0; w < 8; w++) { s += fred[w]; g += ired[w]; l += ired[8 + w]; }
        s += (float)(g - T_DROP) * __expf(k2f16(vhi) * invtau)
           + (float)(l - T_DROP) * __expf(k2f16(vlo) * invtau);
        g_rowlog[row] = logf(s);
    }
}

// ---------------------------------------------------------------------------
// 4) Final reduction (coalesced diag via g_diag)
// ---------------------------------------------------------------------------
__global__ void final_kernel(const float* __restrict__ tau_ptr, float* __restrict__ out) {
    int tid = threadIdx.x;
    double invtau = 1.0 / (double)(*tau_ptr);
    double acc = 0.0;
    for (int i = tid; i < N_ROWS; i += 256) {
        acc += 0.5 * ((double)g_rowlog[i] + (double)g_rowlog[N_ROWS + i])
             - (double)g_diag[i] * invtau;
    }
#pragma unroll
    for (int o = 16; o; o >>= 1) acc += __shfl_xor_sync(0xffffffffu, acc, o);
    __shared__ double dred[8];
    if ((tid & 31) == 0) dred[tid >> 5] = acc;
    __syncthreads();
    if (tid == 0) {
        double s = 0.0;
        for (int w = 0; w < 8; w++) s += dred[w];
        out[0] = (float)(s / (double)N_ROWS);
    }
}

// ---------------------------------------------------------------------------
extern "C" void kernel_launch(void* const* d_in, const int* in_sizes, int n_in,
                              void* d_out, int out_size) {
    const float* h1  = (const float*)d_in[0];
    const float* h2  = (const float*)d_in[1];
    const float* tau = (const float*)d_in[3];
    float* out = (float*)d_out;

    cudaFuncSetAttribute(gram_mma_kernel, cudaFuncAttributeMaxDynamicSharedMemorySize, SMEM_GEMM);

    normalize_kernel<<<TWO_N / 2, 128>>>(h1, h2);
    gram_mma_kernel<<<dim3(64, 64), 256, SMEM_GEMM>>>();
    row_select_kernel<<<TWO_N, 256>>>(tau);
    final_kernel<<<1, 256>>>(tau, out);
}